// round 4
// baseline (speedup 1.0000x reference)
#include <cuda_runtime.h>
#include <math.h>

#define Bsz  32
#define Tlen 512
#define Idim 1024
#define Hdim 1024
#define G4   4096

// ---------------- device scratch ----------------
__device__ float g_xw[(size_t)Tlen * Bsz * G4];   // [t][b][4H]
__device__ float g_wt[(size_t)Idim * G4];         // W_ih transposed: [k][n]
__device__ float g_h2[2][Hdim * Bsz];             // pair-interleaved h
__device__ unsigned int g_bar;

// ---------------- helpers ----------------
__device__ __forceinline__ void fma2(unsigned long long& acc,
                                     unsigned long long a, unsigned long long b)
{
    asm volatile("fma.rn.f32x2 %0, %1, %2, %0;" : "+l"(acc) : "l"(a), "l"(b));
}
__device__ __forceinline__ unsigned long long pack2(float lo, float hi)
{
    unsigned long long r;
    asm("mov.b64 %0, {%1, %2};" : "=l"(r) : "f"(lo), "f"(hi));
    return r;
}
__device__ __forceinline__ void unpack2(unsigned long long p, float& lo, float& hi)
{
    asm("mov.b64 {%0, %1}, %2;" : "=f"(lo), "=f"(hi) : "l"(p));
}
__device__ __forceinline__ void lds_v2u64(unsigned addr,
                                          unsigned long long& a, unsigned long long& b)
{
    asm volatile("ld.shared.v2.u64 {%0, %1}, [%2];" : "=l"(a), "=l"(b) : "r"(addr));
}
__device__ __forceinline__ unsigned long long lds_u64(unsigned addr)
{
    unsigned long long r;
    asm volatile("ld.shared.b64 %0, [%1];" : "=l"(r) : "r"(addr));
    return r;
}
__device__ __forceinline__ void cp_async16(unsigned dst, const void* src)
{
    asm volatile("cp.async.cg.shared.global [%0], [%1], 16;" :: "r"(dst), "l"(src));
}
#define CP_COMMIT()  asm volatile("cp.async.commit_group;")
#define CP_WAIT(N)   asm volatile("cp.async.wait_group %0;" :: "n"(N))

// =======================================================================
// Kernel 0: transpose W_ih -> g_wt[k][n]; also resets grid barrier.
// =======================================================================
__global__ void __launch_bounds__(256) transpose_wih_kernel(const float* __restrict__ W)
{
    __shared__ float tile[32][33];
    if (blockIdx.x == 0 && blockIdx.y == 0 && threadIdx.x == 0) g_bar = 0u;
    const int x  = threadIdx.x & 31;
    const int y4 = (threadIdx.x >> 5) << 2;
    const int nb = blockIdx.x * 32;
    const int kb = blockIdx.y * 32;
#pragma unroll
    for (int j = 0; j < 4; j++)
        tile[y4 + j][x] = W[(size_t)(nb + y4 + j) * Idim + kb + x];
    __syncthreads();
#pragma unroll
    for (int j = 0; j < 4; j++)
        g_wt[(size_t)(kb + y4 + j) * G4 + nb + x] = tile[x][y4 + j];
}

// =======================================================================
// Phase 1: g_xw = x @ Wih^T + b.  128x128 tile, BK=16, 256 threads,
// 8x8 microtile in f32x2. A staged pre-duplicated {a,a}; B via cp.async.
// =======================================================================
#define P1_BK 16

__global__ void __launch_bounds__(256, 2) gemm_xw_kernel(
    const float* __restrict__ x, const float* __restrict__ bias)
{
    __shared__ float As2[2][P1_BK][256];   // [k][2m dup]
    __shared__ float Bs [2][P1_BK][128];   // [k][n]

    const int tid  = threadIdx.x;
    const int bn   = blockIdx.x * 128;
    const int bm   = blockIdx.y * 128;
    const int tx8  = (tid & 15) << 3;
    const int ty8  = (tid >> 4) << 3;
    const int srow = tid >> 1;            // A staging row (m)
    const int skq  = (tid & 1) << 3;      // A staging k-offset
    const int kk   = tid & 15;            // B staging k-row
    const int seg  = tid >> 4;            // B staging n-segment

    const unsigned as_base = (unsigned)__cvta_generic_to_shared(&As2[0][0][0]);
    const unsigned bs_base = (unsigned)__cvta_generic_to_shared(&Bs[0][0][0]);

    const float* Ag = x + (size_t)(bm + srow) * Idim + skq;

    // ---- pre-loop: B(0) via cp.async, A(0) via regs, then A(1) prefetch ----
    float4 a0c = *(const float4*)(Ag + 0);
    float4 a1c = *(const float4*)(Ag + 4);
    {
        const float* bsrc = g_wt + (size_t)kk * G4 + bn + seg * 8;
        unsigned bdst = bs_base + (unsigned)(((kk) * 128 + seg * 8) * 4);
        cp_async16(bdst,      bsrc);
        cp_async16(bdst + 16, bsrc + 4);
        CP_COMMIT();
    }
    {
        float va[8] = {a0c.x, a0c.y, a0c.z, a0c.w, a1c.x, a1c.y, a1c.z, a1c.w};
#pragma unroll
        for (int j = 0; j < 8; j++)
            *(unsigned long long*)&As2[0][skq + j][2 * srow] = pack2(va[j], va[j]);
    }
    a0c = *(const float4*)(Ag + 16);
    a1c = *(const float4*)(Ag + 20);
    CP_WAIT(0);
    __syncthreads();

    unsigned long long acc[8][4];
#pragma unroll
    for (int i = 0; i < 8; i++)
#pragma unroll
        for (int j = 0; j < 4; j++) acc[i][j] = 0ull;

    int p = 0;
    for (int kt = 0; kt < Idim / P1_BK; kt++) {
        if (kt + 1 < Idim / P1_BK) {
            // B(kt+1) cp.async into buf p^1
            const float* bsrc = g_wt + (size_t)((kt + 1) * P1_BK + kk) * G4 + bn + seg * 8;
            unsigned bdst = bs_base +
                (unsigned)((((p ^ 1) * P1_BK + kk) * 128 + seg * 8) * 4);
            cp_async16(bdst,      bsrc);
            cp_async16(bdst + 16, bsrc + 4);
            CP_COMMIT();
            // A(kt+1) dup-store into buf p^1
            float va[8] = {a0c.x, a0c.y, a0c.z, a0c.w, a1c.x, a1c.y, a1c.z, a1c.w};
#pragma unroll
            for (int j = 0; j < 8; j++)
                *(unsigned long long*)&As2[p ^ 1][skq + j][2 * srow] = pack2(va[j], va[j]);
            if (kt + 2 < Idim / P1_BK) {
                a0c = *(const float4*)(Ag + (kt + 2) * P1_BK);
                a1c = *(const float4*)(Ag + (kt + 2) * P1_BK + 4);
            }
        }

#pragma unroll
        for (int k = 0; k < P1_BK; k++) {
            unsigned aaddr = as_base +
                (unsigned)(((p * P1_BK + k) * 256 + 2 * ty8) * 4);
            unsigned long long pa0, pa1, pa2, pa3, pa4, pa5, pa6, pa7;
            lds_v2u64(aaddr,      pa0, pa1);
            lds_v2u64(aaddr + 16, pa2, pa3);
            lds_v2u64(aaddr + 32, pa4, pa5);
            lds_v2u64(aaddr + 48, pa6, pa7);
            unsigned baddr = bs_base +
                (unsigned)(((p * P1_BK + k) * 128 + tx8) * 4);
            unsigned long long b0, b1, b2, b3;
            lds_v2u64(baddr,      b0, b1);
            lds_v2u64(baddr + 16, b2, b3);
            fma2(acc[0][0], pa0, b0); fma2(acc[0][1], pa0, b1);
            fma2(acc[0][2], pa0, b2); fma2(acc[0][3], pa0, b3);
            fma2(acc[1][0], pa1, b0); fma2(acc[1][1], pa1, b1);
            fma2(acc[1][2], pa1, b2); fma2(acc[1][3], pa1, b3);
            fma2(acc[2][0], pa2, b0); fma2(acc[2][1], pa2, b1);
            fma2(acc[2][2], pa2, b2); fma2(acc[2][3], pa2, b3);
            fma2(acc[3][0], pa3, b0); fma2(acc[3][1], pa3, b1);
            fma2(acc[3][2], pa3, b2); fma2(acc[3][3], pa3, b3);
            fma2(acc[4][0], pa4, b0); fma2(acc[4][1], pa4, b1);
            fma2(acc[4][2], pa4, b2); fma2(acc[4][3], pa4, b3);
            fma2(acc[5][0], pa5, b0); fma2(acc[5][1], pa5, b1);
            fma2(acc[5][2], pa5, b2); fma2(acc[5][3], pa5, b3);
            fma2(acc[6][0], pa6, b0); fma2(acc[6][1], pa6, b1);
            fma2(acc[6][2], pa6, b2); fma2(acc[6][3], pa6, b3);
            fma2(acc[7][0], pa7, b0); fma2(acc[7][1], pa7, b1);
            fma2(acc[7][2], pa7, b2); fma2(acc[7][3], pa7, b3);
        }

        if (kt + 1 < Idim / P1_BK) {
            CP_WAIT(0);
            __syncthreads();
            p ^= 1;
        }
    }

    float4 bb0 = *(const float4*)&bias[bn + tx8];
    float4 bb1 = *(const float4*)&bias[bn + tx8 + 4];
#pragma unroll
    for (int i = 0; i < 8; i++) {
        int m = bm + ty8 + i;
        int t = m & (Tlen - 1);
        int b = m >> 9;
        float4 o0, o1;
        unpack2(acc[i][0], o0.x, o0.y);
        unpack2(acc[i][1], o0.z, o0.w);
        unpack2(acc[i][2], o1.x, o1.y);
        unpack2(acc[i][3], o1.z, o1.w);
        o0.x += bb0.x; o0.y += bb0.y; o0.z += bb0.z; o0.w += bb0.w;
        o1.x += bb1.x; o1.y += bb1.y; o1.z += bb1.z; o1.w += bb1.w;
        float* dst = &g_xw[(size_t)t * (Bsz * G4) + (size_t)b * G4 + bn + tx8];
        *(float4*)(dst + 0) = o0;
        *(float4*)(dst + 4) = o1;
    }
}

// =======================================================================
// Phase 2: persistent recurrence. 128 blocks x 128 threads.
// =======================================================================
#define NBLK 128
#define SH_W_FLOATS (32 * 1024)
#define SH_H_FLOATS (2 * 128 * 32)
#define SMEM_BYTES ((SH_W_FLOATS + SH_H_FLOATS) * 4)

__device__ __forceinline__ void grid_barrier(unsigned target)
{
    __syncthreads();
    if (threadIdx.x == 0) {
        __threadfence();   // publish block's global stores (cumulative w/ bar)
        asm volatile("red.release.gpu.global.add.u32 [%0], %1;"
                     :: "l"(&g_bar), "r"(1u) : "memory");
        unsigned v;
        do {
            asm volatile("ld.acquire.gpu.global.u32 %0, [%1];"
                         : "=r"(v) : "l"(&g_bar) : "memory");
        } while (v < target);
    }
    __syncthreads();
}

__device__ __forceinline__ float sigmoidf_(float v) { return 1.f / (1.f + expf(-v)); }

__global__ void __launch_bounds__(128, 1) lstm_rec_kernel(
    const float* __restrict__ Whh, float* __restrict__ out)
{
    extern __shared__ float smem[];
    float* sw = smem;                    // [32 rows][1024]
    const int tid  = threadIdx.x;
    const int bid  = blockIdx.x;
    const int wi   = tid >> 5;
    const int lane = tid & 31;
    const int hc0  = (bid << 3) + (wi << 1);

    const unsigned sw_base = (unsigned)__cvta_generic_to_shared(smem);
    const unsigned sh_base = sw_base + SH_W_FLOATS * 4u;

    for (int idx = tid; idx < 32 * 256; idx += 128) {
        int r  = idx >> 8;
        int c4 = (idx & 255) << 2;
        int g  = r >> 3, wl = r & 7;
        float4 v = *(const float4*)(Whh + (size_t)(g * Hdim + (bid << 3) + wl) * Hdim + c4);
        *(float4*)(sw + r * 1024 + c4) = v;
    }

    const int hslot = (hc0 >> 1) * 64 + lane * 2;
    *(unsigned long long*)&g_h2[0][hslot] = 0ull;

    unsigned wb[4][2];
#pragma unroll
    for (int g = 0; g < 4; g++)
#pragma unroll
        for (int c = 0; c < 2; c++)
            wb[g][c] = sw_base + (unsigned)(((g * 8 + (wi << 1) + c) * 1024) * 4);

    const float* xwp = g_xw + (size_t)lane * G4 + hc0;
    float2 xv[4];
#pragma unroll
    for (int g = 0; g < 4; g++) xv[g] = *(const float2*)(xwp + g * 1024);

    float cs0 = 0.f, cs1 = 0.f;
    unsigned target = NBLK;
    grid_barrier(target);

    for (int t = 0; t < Tlen; t++) {
        const char*  hTr = (const char*)&g_h2[t & 1][0];
        float*       hTw = &g_h2[(t + 1) & 1][0];

        unsigned long long a[4][2];
#pragma unroll
        for (int g = 0; g < 4; g++) {
            a[g][0] = pack2(xv[g].x, 0.f);
            a[g][1] = pack2(xv[g].y, 0.f);
        }

        // prefetch chunks 0 and 1 via cp.async (L1-bypassing .cg)
#pragma unroll
        for (int m = 0; m < 8; m++)
            cp_async16(sh_base + (unsigned)(m * 2048 + tid * 16),
                       hTr + m * 2048 + tid * 16);
        CP_COMMIT();
#pragma unroll
        for (int m = 0; m < 8; m++)
            cp_async16(sh_base + (unsigned)(16384 + m * 2048 + tid * 16),
                       hTr + 16384 + m * 2048 + tid * 16);
        CP_COMMIT();

        for (int ch = 0; ch < 8; ch++) {
            if (ch < 7) { CP_WAIT(1); } else { CP_WAIT(0); }
            __syncthreads();

            const int p = ch & 1;
            const unsigned shp = sh_base + (unsigned)(p * 16384) + (unsigned)(lane * 8);
            const unsigned wof = (unsigned)(ch * 512);
#pragma unroll 8
            for (int k4 = 0; k4 < 32; k4++) {
                unsigned long long h01 = lds_u64(shp + (unsigned)((k4 * 2 + 0) * 256));
                unsigned long long h23 = lds_u64(shp + (unsigned)((k4 * 2 + 1) * 256));
                unsigned long long w01, w23;
#pragma unroll
                for (int g = 0; g < 4; g++) {
                    lds_v2u64(wb[g][0] + wof + (unsigned)(k4 * 16), w01, w23);
                    fma2(a[g][0], w01, h01); fma2(a[g][0], w23, h23);
                    lds_v2u64(wb[g][1] + wof + (unsigned)(k4 * 16), w01, w23);
                    fma2(a[g][1], w01, h01); fma2(a[g][1], w23, h23);
                }
            }
            __syncthreads();

            if (ch + 2 < 8) {
#pragma unroll
                for (int m = 0; m < 8; m++)
                    cp_async16(sh_base + (unsigned)(p * 16384 + m * 2048 + tid * 16),
                               hTr + (ch + 2) * 16384 + m * 2048 + tid * 16);
                CP_COMMIT();
            }
        }

        float lo, hi;
        unpack2(a[0][0], lo, hi); float zi0 = lo + hi;
        unpack2(a[1][0], lo, hi); float zf0 = lo + hi;
        unpack2(a[2][0], lo, hi); float zg0 = lo + hi;
        unpack2(a[3][0], lo, hi); float zo0 = lo + hi;
        unpack2(a[0][1], lo, hi); float zi1 = lo + hi;
        unpack2(a[1][1], lo, hi); float zf1 = lo + hi;
        unpack2(a[2][1], lo, hi); float zg1 = lo + hi;
        unpack2(a[3][1], lo, hi); float zo1 = lo + hi;

        cs0 = fmaf(sigmoidf_(zf0), cs0, sigmoidf_(zi0) * tanhf(zg0));
        cs1 = fmaf(sigmoidf_(zf1), cs1, sigmoidf_(zi1) * tanhf(zg1));
        float hv0 = sigmoidf_(zo0) * tanhf(cs0);
        float hv1 = sigmoidf_(zo1) * tanhf(cs1);

        *(unsigned long long*)&hTw[hslot] = pack2(hv0, hv1);
        float2 ov; ov.x = hv0; ov.y = hv1;
        *(float2*)&out[(size_t)lane * (Tlen * Hdim) + (size_t)t * Hdim + hc0] = ov;

        if (t + 1 < Tlen) {
            const float* nx = xwp + (size_t)(t + 1) * (Bsz * G4);
#pragma unroll
            for (int g = 0; g < 4; g++) xv[g] = *(const float2*)(nx + g * 1024);
        }

        target += NBLK;
        grid_barrier(target);
    }
}

// =======================================================================
extern "C" void kernel_launch(void* const* d_in, const int* in_sizes, int n_in,
                              void* d_out, int out_size)
{
    const float* x    = (const float*)d_in[0];
    const float* Wih  = (const float*)d_in[1];
    const float* Whh  = (const float*)d_in[2];
    const float* bias = (const float*)d_in[3];
    float* out = (float*)d_out;

    cudaFuncSetAttribute(lstm_rec_kernel,
                         cudaFuncAttributeMaxDynamicSharedMemorySize, SMEM_BYTES);

    dim3 gt(G4 / 32, Idim / 32);             // (128, 32)
    transpose_wih_kernel<<<gt, 256>>>(Wih);

    dim3 g1(G4 / 128, (Bsz * Tlen) / 128);   // (32, 128)
    gemm_xw_kernel<<<g1, 256>>>(x, bias);

    lstm_rec_kernel<<<NBLK, 128, SMEM_BYTES>>>(Whh, out);
}